// round 12
// baseline (speedup 1.0000x reference)
#include <cuda_runtime.h>
#include <cuda_fp16.h>
#include <cstdint>

// Shapes (fixed by the problem)
#define BB 4
#define CC 256
#define TT 2048
#define HH 8
#define DD 32
#define M3 768   // 3*C

#define LOG2E 1.4426950408889634f

// Scratch (device globals; no allocation in kernel_launch)
__device__ __half g_nh[BB * CC * TT];             // norm (fp16)
__device__ __half g_wqh[M3 * CC];                 // qkv_w (fp16)
__device__ __half g_woh[CC * CC];                 // out_w (fp16)
__device__ __half g_sph[BB * HH * 3 * DD * TT];   // qkv (fp16)
__device__ __half g_ath[BB * CC * TT];            // attn out (fp16)

// ---------------------------------------------------------------------------
// Helpers
// ---------------------------------------------------------------------------
__device__ __forceinline__ uint32_t su(const void* p) {
    uint32_t a;
    asm("{ .reg .u64 t; cvta.to.shared.u64 t, %1; cvt.u32.u64 %0, t; }"
        : "=r"(a) : "l"(p));
    return a;
}

__device__ __forceinline__ void ldsm4(uint32_t& d0, uint32_t& d1,
                                      uint32_t& d2, uint32_t& d3, uint32_t addr) {
    asm volatile("ldmatrix.sync.aligned.m8n8.x4.shared.b16 {%0,%1,%2,%3}, [%4];"
                 : "=r"(d0), "=r"(d1), "=r"(d2), "=r"(d3) : "r"(addr));
}

__device__ __forceinline__ void ldsm4t(uint32_t& d0, uint32_t& d1,
                                       uint32_t& d2, uint32_t& d3, uint32_t addr) {
    asm volatile("ldmatrix.sync.aligned.m8n8.x4.trans.shared.b16 {%0,%1,%2,%3}, [%4];"
                 : "=r"(d0), "=r"(d1), "=r"(d2), "=r"(d3) : "r"(addr));
}

__device__ __forceinline__ void mma16816(float* c,
                                         uint32_t a0, uint32_t a1, uint32_t a2, uint32_t a3,
                                         uint32_t b0, uint32_t b1) {
    asm volatile("mma.sync.aligned.m16n8k16.row.col.f32.f16.f16.f32 "
                 "{%0,%1,%2,%3}, {%4,%5,%6,%7}, {%8,%9}, {%0,%1,%2,%3};"
                 : "+f"(c[0]), "+f"(c[1]), "+f"(c[2]), "+f"(c[3])
                 : "r"(a0), "r"(a1), "r"(a2), "r"(a3), "r"(b0), "r"(b1));
}

// pack {x -> low half, y -> high half} as f16x2
__device__ __forceinline__ uint32_t pack2f(float x, float y) {
    uint32_t r;
    asm("cvt.rn.f16x2.f32 %0, %1, %2;" : "=r"(r) : "f"(y), "f"(x));
    return r;
}

__device__ __forceinline__ uint32_t ex2h2(uint32_t x) {
    uint32_t r;
    asm("ex2.approx.f16x2 %0, %1;" : "=r"(r) : "r"(x));
    return r;
}

__device__ __forceinline__ uint32_t hadd2(uint32_t a, uint32_t b) {
    uint32_t r;
    asm("add.rn.f16x2 %0, %1, %2;" : "=r"(r) : "r"(a), "r"(b));
    return r;
}

__device__ __forceinline__ void cpa16(uint32_t s, const void* g) {
    asm volatile("cp.async.cg.shared.global [%0], [%1], 16;" :: "r"(s), "l"(g));
}

// ---------------------------------------------------------------------------
// Kernel 0: weights -> fp16
// ---------------------------------------------------------------------------
__global__ void split_w(const float* __restrict__ qw, const float* __restrict__ ow) {
    int i = blockIdx.x * 256 + threadIdx.x;
    if (i < M3 * CC) g_wqh[i] = __float2half(qw[i]);
    if (i < CC * CC) g_woh[i] = __float2half(ow[i]);
}

// ---------------------------------------------------------------------------
// Kernel 1: GroupNorm -> fp16 [b][c][t]
// ---------------------------------------------------------------------------
__global__ void gn_kernel(const float* __restrict__ x,
                          const float* __restrict__ w,
                          const float* __restrict__ bias) {
    int bg = blockIdx.x;
    int bb = bg >> 5, g = bg & 31;
    const float4* xp = (const float4*)(x + ((size_t)bb * CC + g * 8) * TT);
    int tid = threadIdx.x;

    float s = 0.f, s2 = 0.f;
    for (int i = tid; i < 4096; i += 256) {
        float4 v = xp[i];
        s  += v.x + v.y + v.z + v.w;
        s2 += v.x * v.x + v.y * v.y + v.z * v.z + v.w * v.w;
    }
    __shared__ float rs[256], rs2[256];
    rs[tid] = s; rs2[tid] = s2;
    __syncthreads();
    for (int off = 128; off > 0; off >>= 1) {
        if (tid < off) { rs[tid] += rs[tid + off]; rs2[tid] += rs2[tid + off]; }
        __syncthreads();
    }
    float mu   = rs[0] * (1.f / 16384.f);
    float var  = rs2[0] * (1.f / 16384.f) - mu * mu;
    float rstd = rsqrtf(var + 1e-5f);

    size_t ob = ((size_t)bb * CC + g * 8) * TT;
    for (int i = tid; i < 4096; i += 256) {
        int c = g * 8 + (i >> 9);
        float wc = w[c] * rstd;
        float bc = bias[c] - mu * wc;
        float4 v = xp[i];
        uint32_t h01 = pack2f(v.x * wc + bc, v.y * wc + bc);
        uint32_t h23 = pack2f(v.z * wc + bc, v.w * wc + bc);
        *(uint2*)(g_nh + ob + (size_t)i * 4) = make_uint2(h01, h23);
    }
}

// ---------------------------------------------------------------------------
// Kernel 2: QKV projection, fp16 mma GEMM, M=32 per warp.
// ---------------------------------------------------------------------------
__global__ void __launch_bounds__(256) qkv_gemm_kernel() {
    int batch = blockIdx.z;
    int n0 = blockIdx.x * 64, mb = blockIdx.y * 256;
    const __half* Bh_g = g_nh + (size_t)batch * CC * TT;

    __shared__ __align__(16) __half Ah[256][40];
    __shared__ __align__(16) __half Bh[32][72];

    int tid  = threadIdx.x;
    int lane = tid & 31;
    int warp = tid >> 5;
    int m0   = warp * 32;

    float Sf[2][8][4] = {};

    int a_r = lane & 15, a_h = (lane >> 4) * 8;
    int b_d = ((lane >> 3) & 1) * 8 + (lane & 7);
    int b_j = (lane >> 4);

    for (int k0 = 0; k0 < CC; k0 += 32) {
        __syncthreads();
        {
            #pragma unroll
            for (int t4 = 0; t4 < 4; t4++) {
                int f = tid + t4 * 256;
                int r = f >> 2, c = (f & 3) * 8;
                *(uint4*)&Ah[r][c] = *(const uint4*)(g_wqh + (size_t)(mb + r) * CC + k0 + c);
            }
            int r = tid >> 3, c = (tid & 7) * 8;
            *(uint4*)&Bh[r][c] = *(const uint4*)(Bh_g + (size_t)(k0 + r) * TT + n0 + c);
        }
        __syncthreads();
        #pragma unroll
        for (int kc = 0; kc < 2; kc++) {
            int kb = kc * 16;
            uint32_t a[2][4];
            #pragma unroll
            for (int hh = 0; hh < 2; hh++)
                ldsm4(a[hh][0], a[hh][1], a[hh][2], a[hh][3],
                      su(&Ah[m0 + hh * 16 + a_r][kb + a_h]));
            #pragma unroll
            for (int jj = 0; jj < 8; jj += 2) {
                int cb = (jj + b_j) * 8;
                uint32_t k0r, k1r, k2r, k3r;
                ldsm4t(k0r, k1r, k2r, k3r, su(&Bh[kb + b_d][cb]));
                #pragma unroll
                for (int hh = 0; hh < 2; hh++) {
                    mma16816(Sf[hh][jj],     a[hh][0], a[hh][1], a[hh][2], a[hh][3], k0r, k1r);
                    mma16816(Sf[hh][jj + 1], a[hh][0], a[hh][1], a[hh][2], a[hh][3], k2r, k3r);
                }
            }
        }
    }

    int r0 = lane >> 2, tig = lane & 3;
    #pragma unroll
    for (int hh = 0; hh < 2; hh++) {
        #pragma unroll
        for (int half = 0; half < 2; half++) {
            int o = mb + m0 + hh * 16 + r0 + half * 8;
            int hd = o / 96, rr = o % 96;
            int role = rr >> 5, d = rr & 31;
            float sc = (role == 0) ? (LOG2E / 16.0f) : 1.0f;
            size_t base = ((((size_t)batch * HH + hd) * 3 + role) * DD + d) * TT + n0 + tig * 2;
            #pragma unroll
            for (int j = 0; j < 8; j++) {
                *(uint32_t*)(g_sph + base + j * 8) =
                    pack2f(Sf[hh][j][2 * half] * sc, Sf[hh][j][2 * half + 1] * sc);
            }
        }
    }
}

// ---------------------------------------------------------------------------
// Kernel 3: flash attention — fp16, L-tile 128 (8 warps, M=16/warp),
// X-tile 128 per cp.async stage (2x64 compute chunks): half the barriers of
// R9/R10, and smem sized so the whole 512-block grid fits in ONE wave
// (43.5 KB/block -> 5 resident blocks/SM >= 3.46 required).
// ---------------------------------------------------------------------------
struct KVStage {
    __half Kh[32][136], Vh[32][136];
};
#define ROWB 272   // bytes per smem row (136 halves)

__global__ void __launch_bounds__(256) attn_kernel() {
    int lt0 = blockIdx.x * 128, h = blockIdx.y, batch = blockIdx.z;
    size_t hb = ((size_t)batch * HH + h) * 3 * DD * TT;
    const __half* qhp = g_sph + hb;
    const __half* khp = qhp + DD * TT;
    const __half* vhp = qhp + 2 * DD * TT;

    __shared__ __align__(16) __half Qh[32][136];
    __shared__ __align__(16) KVStage st[2];

    int tid  = threadIdx.x;
    int lane = tid & 31;
    int warp = tid >> 5;      // 0..7
    int m0   = warp * 16;

    // ---- loop-invariant cp.async addresses (K,V x 2 column-halves) ----
    int row = tid >> 3;               // 0..31 (d)
    int cbl = (tid & 7) * 8;          // 0..56 (x within first 64)
    const __half* gK = khp + (size_t)row * TT + cbl;
    const __half* gV = vhp + (size_t)row * TT + cbl;
    uint32_t aK[2], aV[2];
    #pragma unroll
    for (int s = 0; s < 2; s++) {
        aK[s] = su(&st[s].Kh[row][cbl]);
        aV[s] = su(&st[s].Vh[row][cbl]);
    }

    // prefetch stage 0 (full 128 columns)
    cpa16(aK[0], gK); cpa16(aK[0] + 128, gK + 64);
    cpa16(aV[0], gV); cpa16(aV[0] + 128, gV + 64);
    asm volatile("cp.async.commit_group;" ::: "memory");

    // ---- Q tile [32 d][128 l] -> smem ----
    #pragma unroll
    for (int t2 = 0; t2 < 2; t2++) {
        int f = tid + t2 * 256;
        int d = f >> 4, c = (f & 15) * 8;
        *(uint4*)&Qh[d][c] = *(const uint4*)(qhp + (size_t)d * TT + lt0 + c);
    }
    __syncthreads();

    // ---- Q fragments (loop-invariant) ----
    int a_d = ((lane >> 4) & 1) * 8 + (lane & 7);
    int a_c = m0 + ((lane >> 3) & 1) * 8;
    uint32_t qf[2][4];
    #pragma unroll
    for (int kc = 0; kc < 2; kc++) {
        ldsm4t(qf[kc][0], qf[kc][1], qf[kc][2], qf[kc][3], su(&Qh[kc * 16 + a_d][a_c]));
    }

    // ---- loop-invariant ldsm base addresses ----
    int b_d = ((lane >> 3) & 1) * 8 + (lane & 7);
    int b_j = (lane >> 4);
    int b4 = lane & 7;
    int bg = lane >> 3;
    uint32_t baseK[2], baseV[2];
    #pragma unroll
    for (int s = 0; s < 2; s++) {
        baseK[s] = su(&st[s].Kh[0][0]) + b_d * ROWB + b_j * 16;
        baseV[s] = su(&st[s].Vh[0][0]) + ((bg >> 1) * 8 + b4) * ROWB + (bg & 1) * 16;
    }

    float sum0 = 0.f, sum1 = 0.f;
    float Of[4][4] = {};

    for (int xt = 0; xt < 16; xt++) {
        if (xt + 1 < 16) {
            int xo = (xt + 1) * 128;
            int s = (xt + 1) & 1;
            cpa16(aK[s], gK + xo); cpa16(aK[s] + 128, gK + xo + 64);
            cpa16(aV[s], gV + xo); cpa16(aV[s] + 128, gV + xo + 64);
            asm volatile("cp.async.commit_group;" ::: "memory");
            asm volatile("cp.async.wait_group 1;" ::: "memory");
        } else {
            asm volatile("cp.async.wait_group 0;" ::: "memory");
        }
        __syncthreads();
        int sb = xt & 1;

        // ---- two 64-column compute chunks per staged 128-column tile ----
        #pragma unroll
        for (int hx = 0; hx < 2; hx++) {
            int ho = hx * 128;   // byte offset for column half

            // S' = Qh Kh (log2e scale folded into Q)
            float Sf[8][4] = {};
            #pragma unroll
            for (int kc = 0; kc < 2; kc++) {
                #pragma unroll
                for (int jj = 0; jj < 8; jj += 2) {
                    uint32_t k0, k1, k2, k3;
                    ldsm4t(k0, k1, k2, k3, baseK[sb] + ho + kc * 16 * ROWB + jj * 16);
                    mma16816(Sf[jj],     qf[kc][0], qf[kc][1], qf[kc][2], qf[kc][3], k0, k1);
                    mma16816(Sf[jj + 1], qf[kc][0], qf[kc][1], qf[kc][2], qf[kc][3], k2, k3);
                }
            }

            // P = 2^(S') packed f16x2 (== mma A-frag), sums, O += P V
            uint32_t acc0 = 0, acc1 = 0;
            #pragma unroll
            for (int kc = 0; kc < 4; kc++) {
                int j0 = 2 * kc, j1 = 2 * kc + 1;
                uint32_t p0 = ex2h2(pack2f(Sf[j0][0], Sf[j0][1]));
                uint32_t p1 = ex2h2(pack2f(Sf[j0][2], Sf[j0][3]));
                uint32_t p2 = ex2h2(pack2f(Sf[j1][0], Sf[j1][1]));
                uint32_t p3 = ex2h2(pack2f(Sf[j1][2], Sf[j1][3]));
                acc0 = hadd2(acc0, p0); acc0 = hadd2(acc0, p2);
                acc1 = hadd2(acc1, p1); acc1 = hadd2(acc1, p3);
                #pragma unroll
                for (int np = 0; np < 2; np++) {
                    uint32_t h0, h1, h2, h3;
                    ldsm4(h0, h1, h2, h3, baseV[sb] + ho + np * 16 * ROWB + kc * 32);
                    mma16816(Of[np * 2],     p0, p1, p2, p3, h0, h1);
                    mma16816(Of[np * 2 + 1], p0, p1, p2, p3, h2, h3);
                }
            }
            {
                __half2 v0 = *(__half2*)&acc0;
                __half2 v1 = *(__half2*)&acc1;
                sum0 += __low2float(v0) + __high2float(v0);
                sum1 += __low2float(v1) + __high2float(v1);
            }
        }
        __syncthreads();   // release buffer for prefetch at iter xt+2
    }

    // ---- final row-sum reduce ----
    sum0 += __shfl_xor_sync(0xffffffffu, sum0, 1);
    sum0 += __shfl_xor_sync(0xffffffffu, sum0, 2);
    sum1 += __shfl_xor_sync(0xffffffffu, sum1, 1);
    sum1 += __shfl_xor_sync(0xffffffffu, sum1, 2);
    float inv0 = 1.f / sum0, inv1 = 1.f / sum1;

    // ---- epilogue: normalize, transpose via smem (alias stages), fp16 store
    float (*Os)[33] = (float(*)[33])&st[0];
    int r0w = lane >> 2, tig = lane & 3;
    #pragma unroll
    for (int nd = 0; nd < 4; nd++) {
        int col = nd * 8 + tig * 2;
        Os[m0 + r0w][col]         = Of[nd][0] * inv0;
        Os[m0 + r0w][col + 1]     = Of[nd][1] * inv0;
        Os[m0 + r0w + 8][col]     = Of[nd][2] * inv1;
        Os[m0 + r0w + 8][col + 1] = Of[nd][3] * inv1;
    }
    __syncthreads();
    size_t ob = ((size_t)batch * CC + h * DD) * TT;
    #pragma unroll
    for (int t4 = 0; t4 < 4; t4++) {
        int f = tid + t4 * 256;
        int d = f >> 5, lq = (f & 31) * 4;
        uint32_t u01 = pack2f(Os[lq][d],     Os[lq + 1][d]);
        uint32_t u23 = pack2f(Os[lq + 2][d], Os[lq + 3][d]);
        *(uint2*)(g_ath + ob + (size_t)d * TT + lt0 + lq) = make_uint2(u01, u23);
    }
}

// ---------------------------------------------------------------------------
// Kernel 4: out projection, pure-fp16 mma GEMM + bias + residual.
// ---------------------------------------------------------------------------
__global__ void __launch_bounds__(256) out_gemm_kernel(const float* __restrict__ ob,
                                                       const float* __restrict__ xres,
                                                       float* __restrict__ out) {
    int batch = blockIdx.z;
    int n0 = blockIdx.x * 64, mb = blockIdx.y * 128;
    const __half* Bh_g = g_ath + (size_t)batch * CC * TT;

    __shared__ __align__(16) __half Ah[128][40];
    __shared__ __align__(16) __half Bh[32][72];

    int tid  = threadIdx.x;
    int lane = tid & 31;
    int warp = tid >> 5;
    int m0   = warp * 16;

    float Sf[8][4] = {};

    int a_r = lane & 15, a_h = (lane >> 4) * 8;
    int b_d = ((lane >> 3) & 1) * 8 + (lane & 7);
    int b_j = (lane >> 4);

    for (int k0 = 0; k0 < CC; k0 += 32) {
        __syncthreads();
        {
            #pragma unroll
            for (int t2 = 0; t2 < 2; t2++) {
                int f = tid + t2 * 256;
                int r = f >> 2, c = (f & 3) * 8;
                *(uint4*)&Ah[r][c] = *(const uint4*)(g_woh + (size_t)(mb + r) * CC + k0 + c);
            }
            int r = tid >> 3, c = (tid & 7) * 8;
            *(uint4*)&Bh[r][c] = *(const uint4*)(Bh_g + (size_t)(k0 + r) * TT + n0 + c);
        }
        __syncthreads();
        #pragma unroll
        for (int kc = 0; kc < 2; kc++) {
            int kb = kc * 16;
            uint32_t a0, a1, a2, a3;
            ldsm4(a0, a1, a2, a3, su(&Ah[m0 + a_r][kb + a_h]));
            #pragma unroll
            for (int jj = 0; jj < 8; jj += 2) {
                int cb = (jj + b_j) * 8;
                uint32_t k0r, k1r, k2r, k3r;
                ldsm4t(k0r, k1r, k2r, k3r, su(&Bh[kb + b_d][cb]));
                mma16816(Sf[jj],     a0, a1, a2, a3, k0r, k1r);
                mma16816(Sf[jj + 1], a0, a1, a2, a3, k2r, k3r);
            }
        }
    }

    int r0 = lane >> 2, tig = lane & 3;
    #pragma unroll
    for (int half = 0; half < 2; half++) {
        int m = mb + m0 + r0 + half * 8;
        float bsv = ob[m];
        size_t rowoff = ((size_t)batch * CC + m) * TT + n0 + tig * 2;
        #pragma unroll
        for (int j = 0; j < 8; j++) {
            float2 r = *(const float2*)(xres + rowoff + j * 8);
            float2 o = make_float2(Sf[j][2 * half] + bsv + r.x,
                                   Sf[j][2 * half + 1] + bsv + r.y);
            *(float2*)(out + rowoff + j * 8) = o;
        }
    }
}

// ---------------------------------------------------------------------------
extern "C" void kernel_launch(void* const* d_in, const int* in_sizes, int n_in,
                              void* d_out, int out_size) {
    const float* x     = (const float*)d_in[0];
    const float* gn_w  = (const float*)d_in[1];
    const float* gn_b  = (const float*)d_in[2];
    const float* qkv_w = (const float*)d_in[3];
    const float* out_w = (const float*)d_in[4];
    const float* out_b = (const float*)d_in[5];
    float* out = (float*)d_out;

    split_w<<<M3 * CC / 256, 256>>>(qkv_w, out_w);
    gn_kernel<<<BB * 32, 256>>>(x, gn_w, gn_b);
    qkv_gemm_kernel<<<dim3(TT / 64, M3 / 256, BB), 256>>>();
    attn_kernel<<<dim3(TT / 128, HH, BB), 256>>>();
    out_gemm_kernel<<<dim3(TT / 64, CC / 128, BB), 256>>>(out_b, x, out);
}

// round 13
// speedup vs baseline: 1.0892x; 1.0892x over previous
#include <cuda_runtime.h>
#include <cuda_fp16.h>
#include <cstdint>

// Shapes (fixed by the problem)
#define BB 4
#define CC 256
#define TT 2048
#define HH 8
#define DD 32
#define M3 768   // 3*C

#define LOG2E 1.4426950408889634f

// Scratch (device globals; no allocation in kernel_launch)
__device__ __half g_nh[BB * CC * TT];             // norm (fp16)
__device__ __half g_wqh[M3 * CC];                 // qkv_w (fp16)
__device__ __half g_woh[CC * CC];                 // out_w (fp16)
__device__ __half g_sph[BB * HH * 3 * DD * TT];   // qkv (fp16)
__device__ __half g_ath[BB * CC * TT];            // attn out (fp16)

// ---------------------------------------------------------------------------
// Helpers
// ---------------------------------------------------------------------------
__device__ __forceinline__ uint32_t su(const void* p) {
    uint32_t a;
    asm("{ .reg .u64 t; cvta.to.shared.u64 t, %1; cvt.u32.u64 %0, t; }"
        : "=r"(a) : "l"(p));
    return a;
}

__device__ __forceinline__ void ldsm4(uint32_t& d0, uint32_t& d1,
                                      uint32_t& d2, uint32_t& d3, uint32_t addr) {
    asm volatile("ldmatrix.sync.aligned.m8n8.x4.shared.b16 {%0,%1,%2,%3}, [%4];"
                 : "=r"(d0), "=r"(d1), "=r"(d2), "=r"(d3) : "r"(addr));
}

__device__ __forceinline__ void ldsm4t(uint32_t& d0, uint32_t& d1,
                                       uint32_t& d2, uint32_t& d3, uint32_t addr) {
    asm volatile("ldmatrix.sync.aligned.m8n8.x4.trans.shared.b16 {%0,%1,%2,%3}, [%4];"
                 : "=r"(d0), "=r"(d1), "=r"(d2), "=r"(d3) : "r"(addr));
}

// f32-accumulator mma (projection GEMMs)
__device__ __forceinline__ void mma16816(float* c,
                                         uint32_t a0, uint32_t a1, uint32_t a2, uint32_t a3,
                                         uint32_t b0, uint32_t b1) {
    asm volatile("mma.sync.aligned.m16n8k16.row.col.f32.f16.f16.f32 "
                 "{%0,%1,%2,%3}, {%4,%5,%6,%7}, {%8,%9}, {%0,%1,%2,%3};"
                 : "+f"(c[0]), "+f"(c[1]), "+f"(c[2]), "+f"(c[3])
                 : "r"(a0), "r"(a1), "r"(a2), "r"(a3), "r"(b0), "r"(b1));
}

// f16-accumulator mma (attention mainloop): C/D are 2 regs of f16x2, laid out
// identically to the packed pairs we previously built with cvt.rn.f16x2.
__device__ __forceinline__ void mma16816h(uint32_t& d0, uint32_t& d1,
                                          uint32_t a0, uint32_t a1, uint32_t a2, uint32_t a3,
                                          uint32_t b0, uint32_t b1) {
    asm volatile("mma.sync.aligned.m16n8k16.row.col.f16.f16.f16.f16 "
                 "{%0,%1}, {%2,%3,%4,%5}, {%6,%7}, {%0,%1};"
                 : "+r"(d0), "+r"(d1)
                 : "r"(a0), "r"(a1), "r"(a2), "r"(a3), "r"(b0), "r"(b1));
}

// pack {x -> low half, y -> high half} as f16x2
__device__ __forceinline__ uint32_t pack2f(float x, float y) {
    uint32_t r;
    asm("cvt.rn.f16x2.f32 %0, %1, %2;" : "=r"(r) : "f"(y), "f"(x));
    return r;
}

__device__ __forceinline__ uint32_t ex2h2(uint32_t x) {
    uint32_t r;
    asm("ex2.approx.f16x2 %0, %1;" : "=r"(r) : "r"(x));
    return r;
}

__device__ __forceinline__ uint32_t hadd2(uint32_t a, uint32_t b) {
    uint32_t r;
    asm("add.rn.f16x2 %0, %1, %2;" : "=r"(r) : "r"(a), "r"(b));
    return r;
}

__device__ __forceinline__ void cpa16(uint32_t s, const void* g) {
    asm volatile("cp.async.cg.shared.global [%0], [%1], 16;" :: "r"(s), "l"(g));
}

// ---------------------------------------------------------------------------
// Kernel 1: fused weight-convert + GroupNorm.
// Blocks [0, 768): convert qkv_w/out_w to fp16.
// Blocks [768, 896): GroupNorm -> fp16 [b][c][t].
// ---------------------------------------------------------------------------
__global__ void gnsplit_kernel(const float* __restrict__ x,
                               const float* __restrict__ w,
                               const float* __restrict__ bias,
                               const float* __restrict__ qw,
                               const float* __restrict__ ow) {
    int tid = threadIdx.x;
    if (blockIdx.x < 768) {
        int i = blockIdx.x * 256 + tid;
        g_wqh[i] = __float2half(qw[i]);
        if (i < CC * CC) g_woh[i] = __float2half(ow[i]);
        return;
    }
    int bg = blockIdx.x - 768;
    int bb = bg >> 5, g = bg & 31;
    const float4* xp = (const float4*)(x + ((size_t)bb * CC + g * 8) * TT);

    float s = 0.f, s2 = 0.f;
    for (int i = tid; i < 4096; i += 256) {
        float4 v = xp[i];
        s  += v.x + v.y + v.z + v.w;
        s2 += v.x * v.x + v.y * v.y + v.z * v.z + v.w * v.w;
    }
    __shared__ float rs[256], rs2[256];
    rs[tid] = s; rs2[tid] = s2;
    __syncthreads();
    for (int off = 128; off > 0; off >>= 1) {
        if (tid < off) { rs[tid] += rs[tid + off]; rs2[tid] += rs2[tid + off]; }
        __syncthreads();
    }
    float mu   = rs[0] * (1.f / 16384.f);
    float var  = rs2[0] * (1.f / 16384.f) - mu * mu;
    float rstd = rsqrtf(var + 1e-5f);

    size_t ob = ((size_t)bb * CC + g * 8) * TT;
    for (int i = tid; i < 4096; i += 256) {
        int c = g * 8 + (i >> 9);
        float wc = w[c] * rstd;
        float bc = bias[c] - mu * wc;
        float4 v = xp[i];
        uint32_t h01 = pack2f(v.x * wc + bc, v.y * wc + bc);
        uint32_t h23 = pack2f(v.z * wc + bc, v.w * wc + bc);
        *(uint2*)(g_nh + ob + (size_t)i * 4) = make_uint2(h01, h23);
    }
}

// ---------------------------------------------------------------------------
// Kernel 2: QKV projection, fp16 mma GEMM (f32 accum), M=32 per warp.
// ---------------------------------------------------------------------------
__global__ void __launch_bounds__(256) qkv_gemm_kernel() {
    int batch = blockIdx.z;
    int n0 = blockIdx.x * 64, mb = blockIdx.y * 256;
    const __half* Bh_g = g_nh + (size_t)batch * CC * TT;

    __shared__ __align__(16) __half Ah[256][40];
    __shared__ __align__(16) __half Bh[32][72];

    int tid  = threadIdx.x;
    int lane = tid & 31;
    int warp = tid >> 5;
    int m0   = warp * 32;

    float Sf[2][8][4] = {};

    int a_r = lane & 15, a_h = (lane >> 4) * 8;
    int b_d = ((lane >> 3) & 1) * 8 + (lane & 7);
    int b_j = (lane >> 4);

    for (int k0 = 0; k0 < CC; k0 += 32) {
        __syncthreads();
        {
            #pragma unroll
            for (int t4 = 0; t4 < 4; t4++) {
                int f = tid + t4 * 256;
                int r = f >> 2, c = (f & 3) * 8;
                *(uint4*)&Ah[r][c] = *(const uint4*)(g_wqh + (size_t)(mb + r) * CC + k0 + c);
            }
            int r = tid >> 3, c = (tid & 7) * 8;
            *(uint4*)&Bh[r][c] = *(const uint4*)(Bh_g + (size_t)(k0 + r) * TT + n0 + c);
        }
        __syncthreads();
        #pragma unroll
        for (int kc = 0; kc < 2; kc++) {
            int kb = kc * 16;
            uint32_t a[2][4];
            #pragma unroll
            for (int hh = 0; hh < 2; hh++)
                ldsm4(a[hh][0], a[hh][1], a[hh][2], a[hh][3],
                      su(&Ah[m0 + hh * 16 + a_r][kb + a_h]));
            #pragma unroll
            for (int jj = 0; jj < 8; jj += 2) {
                int cb = (jj + b_j) * 8;
                uint32_t k0r, k1r, k2r, k3r;
                ldsm4t(k0r, k1r, k2r, k3r, su(&Bh[kb + b_d][cb]));
                #pragma unroll
                for (int hh = 0; hh < 2; hh++) {
                    mma16816(Sf[hh][jj],     a[hh][0], a[hh][1], a[hh][2], a[hh][3], k0r, k1r);
                    mma16816(Sf[hh][jj + 1], a[hh][0], a[hh][1], a[hh][2], a[hh][3], k2r, k3r);
                }
            }
        }
    }

    int r0 = lane >> 2, tig = lane & 3;
    #pragma unroll
    for (int hh = 0; hh < 2; hh++) {
        #pragma unroll
        for (int half = 0; half < 2; half++) {
            int o = mb + m0 + hh * 16 + r0 + half * 8;
            int hd = o / 96, rr = o % 96;
            int role = rr >> 5, d = rr & 31;
            float sc = (role == 0) ? (LOG2E / 16.0f) : 1.0f;
            size_t base = ((((size_t)batch * HH + hd) * 3 + role) * DD + d) * TT + n0 + tig * 2;
            #pragma unroll
            for (int j = 0; j < 8; j++) {
                *(uint32_t*)(g_sph + base + j * 8) =
                    pack2f(Sf[hh][j][2 * half] * sc, Sf[hh][j][2 * half + 1] * sc);
            }
        }
    }
}

// ---------------------------------------------------------------------------
// Kernel 3: flash attention — f16-accumulator mma mainloop.
// QK emits packed f16x2 S' C-frags == PV A-frag layout (pack stage deleted);
// ex2.f16x2 applies in place. PV accumulates O in f16 (range ~1e2 << 65504).
// Block 256 = 8 warps, L-tile 128, X-tile 64, cp.async double buffer.
// ---------------------------------------------------------------------------
struct KVStage {
    __half Kh[32][72], Vh[32][72];
};
#define ROWB 144   // bytes per smem row (72 halves)

__global__ void __launch_bounds__(256) attn_kernel() {
    int lt0 = blockIdx.x * 128, h = blockIdx.y, batch = blockIdx.z;
    size_t hb = ((size_t)batch * HH + h) * 3 * DD * TT;
    const __half* qhp = g_sph + hb;
    const __half* khp = qhp + DD * TT;
    const __half* vhp = qhp + 2 * DD * TT;

    __shared__ __align__(16) __half Qh[32][136];
    __shared__ __align__(16) KVStage st[2];

    int tid  = threadIdx.x;
    int lane = tid & 31;
    int warp = tid >> 5;      // 0..7
    int m0   = warp * 16;

    // ---- loop-invariant cp.async addresses ----
    int row = tid >> 3;               // 0..31
    int cbl = (tid & 7) * 8;
    const __half* gK = khp + (size_t)row * TT + cbl;
    const __half* gV = vhp + (size_t)row * TT + cbl;
    uint32_t aK[2], aV[2];
    #pragma unroll
    for (int s = 0; s < 2; s++) {
        aK[s] = su(&st[s].Kh[row][cbl]);
        aV[s] = su(&st[s].Vh[row][cbl]);
    }

    // prefetch stage 0
    cpa16(aK[0], gK); cpa16(aV[0], gV);
    asm volatile("cp.async.commit_group;" ::: "memory");

    // ---- Q tile [32 d][128 l] -> smem ----
    #pragma unroll
    for (int t2 = 0; t2 < 2; t2++) {
        int f = tid + t2 * 256;
        int d = f >> 4, c = (f & 15) * 8;
        *(uint4*)&Qh[d][c] = *(const uint4*)(qhp + (size_t)d * TT + lt0 + c);
    }
    __syncthreads();

    // ---- Q fragments (loop-invariant) ----
    int a_d = ((lane >> 4) & 1) * 8 + (lane & 7);
    int a_c = m0 + ((lane >> 3) & 1) * 8;
    uint32_t qf[2][4];
    #pragma unroll
    for (int kc = 0; kc < 2; kc++) {
        ldsm4t(qf[kc][0], qf[kc][1], qf[kc][2], qf[kc][3], su(&Qh[kc * 16 + a_d][a_c]));
    }

    // ---- loop-invariant ldsm base addresses ----
    int b_d = ((lane >> 3) & 1) * 8 + (lane & 7);
    int b_j = (lane >> 4);
    int b4 = lane & 7;
    int bg = lane >> 3;
    uint32_t baseK[2], baseV[2];
    #pragma unroll
    for (int s = 0; s < 2; s++) {
        baseK[s] = su(&st[s].Kh[0][0]) + b_d * ROWB + b_j * 16;
        baseV[s] = su(&st[s].Vh[0][0]) + ((bg >> 1) * 8 + b4) * ROWB + (bg & 1) * 16;
    }

    float sum0 = 0.f, sum1 = 0.f;
    uint32_t Op[4][2] = {};   // f16x2 O accumulators: 4 n8-tiles x {row r, row r+8}

    for (int xt = 0; xt < 32; xt++) {
        if (xt + 1 < 32) {
            int xo = (xt + 1) * 64;
            int s = (xt + 1) & 1;
            cpa16(aK[s], gK + xo); cpa16(aV[s], gV + xo);
            asm volatile("cp.async.commit_group;" ::: "memory");
            asm volatile("cp.async.wait_group 1;" ::: "memory");
        } else {
            asm volatile("cp.async.wait_group 0;" ::: "memory");
        }
        __syncthreads();
        int sb = xt & 1;

        // ---- S' = Qh Kh, f16 accum: C-frags are packed f16x2 ----
        uint32_t Sp[8][2] = {};
        #pragma unroll
        for (int kc = 0; kc < 2; kc++) {
            #pragma unroll
            for (int jj = 0; jj < 8; jj += 2) {
                uint32_t k0, k1, k2, k3;
                ldsm4t(k0, k1, k2, k3, baseK[sb] + kc * 16 * ROWB + jj * 16);
                mma16816h(Sp[jj][0],     Sp[jj][1],
                          qf[kc][0], qf[kc][1], qf[kc][2], qf[kc][3], k0, k1);
                mma16816h(Sp[jj + 1][0], Sp[jj + 1][1],
                          qf[kc][0], qf[kc][1], qf[kc][2], qf[kc][3], k2, k3);
            }
        }

        // ---- P = 2^(S') in place (packed), row sums, O += P V (f16 accum) --
        uint32_t acc0 = 0, acc1 = 0;
        #pragma unroll
        for (int kc = 0; kc < 4; kc++) {
            int j0 = 2 * kc, j1 = 2 * kc + 1;
            uint32_t p0 = ex2h2(Sp[j0][0]);
            uint32_t p1 = ex2h2(Sp[j0][1]);
            uint32_t p2 = ex2h2(Sp[j1][0]);
            uint32_t p3 = ex2h2(Sp[j1][1]);
            acc0 = hadd2(acc0, p0); acc0 = hadd2(acc0, p2);
            acc1 = hadd2(acc1, p1); acc1 = hadd2(acc1, p3);
            #pragma unroll
            for (int np = 0; np < 2; np++) {
                uint32_t h0, h1, h2, h3;
                ldsm4(h0, h1, h2, h3, baseV[sb] + np * 16 * ROWB + kc * 32);
                mma16816h(Op[np * 2][0],     Op[np * 2][1],     p0, p1, p2, p3, h0, h1);
                mma16816h(Op[np * 2 + 1][0], Op[np * 2 + 1][1], p0, p1, p2, p3, h2, h3);
            }
        }
        {
            __half2 v0 = *(__half2*)&acc0;
            __half2 v1 = *(__half2*)&acc1;
            sum0 += __low2float(v0) + __high2float(v0);
            sum1 += __low2float(v1) + __high2float(v1);
        }
        __syncthreads();   // release buffer for prefetch at iter xt+2
    }

    // ---- final row-sum reduce ----
    sum0 += __shfl_xor_sync(0xffffffffu, sum0, 1);
    sum0 += __shfl_xor_sync(0xffffffffu, sum0, 2);
    sum1 += __shfl_xor_sync(0xffffffffu, sum1, 1);
    sum1 += __shfl_xor_sync(0xffffffffu, sum1, 2);
    float inv0 = 1.f / sum0, inv1 = 1.f / sum1;

    // ---- epilogue: unpack O, normalize, transpose via smem, fp16 store ----
    float (*Os)[33] = (float(*)[33])&st[0];
    int r0w = lane >> 2, tig = lane & 3;
    #pragma unroll
    for (int nd = 0; nd < 4; nd++) {
        int col = nd * 8 + tig * 2;
        __half2 o0 = *(__half2*)&Op[nd][0];
        __half2 o1 = *(__half2*)&Op[nd][1];
        Os[m0 + r0w][col]         = __low2float(o0)  * inv0;
        Os[m0 + r0w][col + 1]     = __high2float(o0) * inv0;
        Os[m0 + r0w + 8][col]     = __low2float(o1)  * inv1;
        Os[m0 + r0w + 8][col + 1] = __high2float(o1) * inv1;
    }
    __syncthreads();
    size_t ob = ((size_t)batch * CC + h * DD) * TT;
    #pragma unroll
    for (int t4 = 0; t4 < 4; t4++) {
        int f = tid + t4 * 256;
        int d = f >> 5, lq = (f & 31) * 4;
        uint32_t u01 = pack2f(Os[lq][d],     Os[lq + 1][d]);
        uint32_t u23 = pack2f(Os[lq + 2][d], Os[lq + 3][d]);
        *(uint2*)(g_ath + ob + (size_t)d * TT + lt0 + lq) = make_uint2(u01, u23);
    }
}

// ---------------------------------------------------------------------------
// Kernel 4: out projection, fp16 mma GEMM (f32 accum) + bias + residual.
// ---------------------------------------------------------------------------
__global__ void __launch_bounds__(256) out_gemm_kernel(const float* __restrict__ ob,
                                                       const float* __restrict__ xres,
                                                       float* __restrict__ out) {
    int batch = blockIdx.z;
    int n0 = blockIdx.x * 64, mb = blockIdx.y * 128;
    const __half* Bh_g = g_ath + (size_t)batch * CC * TT;

    __shared__ __align__(16) __half Ah[128][40];
    __shared__ __align__(16) __half Bh[32][72];

    int tid  = threadIdx.x;
    int lane = tid & 31;
    int warp = tid >> 5;
    int m0   = warp * 16;

    float Sf[8][4] = {};

    int a_r = lane & 15, a_h = (lane >> 4) * 8;
    int b_d = ((lane >> 3) & 1) * 8 + (lane & 7);
    int b_j = (lane >> 4);

    for (int k0 = 0; k0 < CC; k0 += 32) {
        __syncthreads();
        {
            #pragma unroll
            for (int t2 = 0; t2 < 2; t2++) {
                int f = tid + t2 * 256;
                int r = f >> 2, c = (f & 3) * 8;
                *(uint4*)&Ah[r][c] = *(const uint4*)(g_woh + (size_t)(mb + r) * CC + k0 + c);
            }
            int r = tid >> 3, c = (tid & 7) * 8;
            *(uint4*)&Bh[r][c] = *(const uint4*)(Bh_g + (size_t)(k0 + r) * TT + n0 + c);
        }
        __syncthreads();
        #pragma unroll
        for (int kc = 0; kc < 2; kc++) {
            int kb = kc * 16;
            uint32_t a0, a1, a2, a3;
            ldsm4(a0, a1, a2, a3, su(&Ah[m0 + a_r][kb + a_h]));
            #pragma unroll
            for (int jj = 0; jj < 8; jj += 2) {
                int cb = (jj + b_j) * 8;
                uint32_t k0r, k1r, k2r, k3r;
                ldsm4t(k0r, k1r, k2r, k3r, su(&Bh[kb + b_d][cb]));
                mma16816(Sf[jj],     a0, a1, a2, a3, k0r, k1r);
                mma16816(Sf[jj + 1], a0, a1, a2, a3, k2r, k3r);
            }
        }
    }

    int r0 = lane >> 2, tig = lane & 3;
    #pragma unroll
    for (int half = 0; half < 2; half++) {
        int m = mb + m0 + r0 + half * 8;
        float bsv = ob[m];
        size_t rowoff = ((size_t)batch * CC + m) * TT + n0 + tig * 2;
        #pragma unroll
        for (int j = 0; j < 8; j++) {
            float2 r = *(const float2*)(xres + rowoff + j * 8);
            float2 o = make_float2(Sf[j][2 * half] + bsv + r.x,
                                   Sf[j][2 * half + 1] + bsv + r.y);
            *(float2*)(out + rowoff + j * 8) = o;
        }
    }
}

// ---------------------------------------------------------------------------
extern "C" void kernel_launch(void* const* d_in, const int* in_sizes, int n_in,
                              void* d_out, int out_size) {
    const float* x     = (const float*)d_in[0];
    const float* gn_w  = (const float*)d_in[1];
    const float* gn_b  = (const float*)d_in[2];
    const float* qkv_w = (const float*)d_in[3];
    const float* out_w = (const float*)d_in[4];
    const float* out_b = (const float*)d_in[5];
    float* out = (float*)d_out;

    gnsplit_kernel<<<896, 256>>>(x, gn_w, gn_b, qkv_w, out_w);
    qkv_gemm_kernel<<<dim3(TT / 64, M3 / 256, BB), 256>>>();
    attn_kernel<<<dim3(TT / 128, HH, BB), 256>>>();
    out_gemm_kernel<<<dim3(TT / 64, CC / 128, BB), 256>>>(out_b, x, out);
}

// round 16
// speedup vs baseline: 1.1150x; 1.0237x over previous
#include <cuda_runtime.h>
#include <cuda_fp16.h>
#include <cstdint>

// Shapes (fixed by the problem)
#define BB 4
#define CC 256
#define TT 2048
#define HH 8
#define DD 32
#define M3 768   // 3*C

#define LOG2E 1.4426950408889634f

// Scratch (device globals; no allocation in kernel_launch)
__device__ __half g_nh[BB * CC * TT];             // norm (fp16)
__device__ __half g_wqh[M3 * CC];                 // qkv_w (fp16)
__device__ __half g_woh[CC * CC];                 // out_w (fp16)
__device__ __half g_sph[BB * HH * 3 * DD * TT];   // qkv (fp16)
__device__ __half g_ath[BB * CC * TT];            // attn out (fp16)

// ---------------------------------------------------------------------------
// Helpers
// ---------------------------------------------------------------------------
__device__ __forceinline__ uint32_t su(const void* p) {
    uint32_t a;
    asm("{ .reg .u64 t; cvta.to.shared.u64 t, %1; cvt.u32.u64 %0, t; }"
        : "=r"(a) : "l"(p));
    return a;
}

__device__ __forceinline__ void ldsm4(uint32_t& d0, uint32_t& d1,
                                      uint32_t& d2, uint32_t& d3, uint32_t addr) {
    asm volatile("ldmatrix.sync.aligned.m8n8.x4.shared.b16 {%0,%1,%2,%3}, [%4];"
                 : "=r"(d0), "=r"(d1), "=r"(d2), "=r"(d3) : "r"(addr));
}

__device__ __forceinline__ void ldsm4t(uint32_t& d0, uint32_t& d1,
                                       uint32_t& d2, uint32_t& d3, uint32_t addr) {
    asm volatile("ldmatrix.sync.aligned.m8n8.x4.trans.shared.b16 {%0,%1,%2,%3}, [%4];"
                 : "=r"(d0), "=r"(d1), "=r"(d2), "=r"(d3) : "r"(addr));
}

// f32-accumulator mma (projection GEMMs)
__device__ __forceinline__ void mma16816(float* c,
                                         uint32_t a0, uint32_t a1, uint32_t a2, uint32_t a3,
                                         uint32_t b0, uint32_t b1) {
    asm volatile("mma.sync.aligned.m16n8k16.row.col.f32.f16.f16.f32 "
                 "{%0,%1,%2,%3}, {%4,%5,%6,%7}, {%8,%9}, {%0,%1,%2,%3};"
                 : "+f"(c[0]), "+f"(c[1]), "+f"(c[2]), "+f"(c[3])
                 : "r"(a0), "r"(a1), "r"(a2), "r"(a3), "r"(b0), "r"(b1));
}

// f16-accumulator mma (attention mainloop)
__device__ __forceinline__ void mma16816h(uint32_t& d0, uint32_t& d1,
                                          uint32_t a0, uint32_t a1, uint32_t a2, uint32_t a3,
                                          uint32_t b0, uint32_t b1) {
    asm volatile("mma.sync.aligned.m16n8k16.row.col.f16.f16.f16.f16 "
                 "{%0,%1}, {%2,%3,%4,%5}, {%6,%7}, {%0,%1};"
                 : "+r"(d0), "+r"(d1)
                 : "r"(a0), "r"(a1), "r"(a2), "r"(a3), "r"(b0), "r"(b1));
}

// pack {x -> low half, y -> high half} as f16x2
__device__ __forceinline__ uint32_t pack2f(float x, float y) {
    uint32_t r;
    asm("cvt.rn.f16x2.f32 %0, %1, %2;" : "=r"(r) : "f"(y), "f"(x));
    return r;
}

__device__ __forceinline__ uint32_t ex2h2(uint32_t x) {
    uint32_t r;
    asm("ex2.approx.f16x2 %0, %1;" : "=r"(r) : "r"(x));
    return r;
}

__device__ __forceinline__ uint32_t hadd2(uint32_t a, uint32_t b) {
    uint32_t r;
    asm("add.rn.f16x2 %0, %1, %2;" : "=r"(r) : "r"(a), "r"(b));
    return r;
}

__device__ __forceinline__ void cpa16(uint32_t s, const void* g) {
    asm volatile("cp.async.cg.shared.global [%0], [%1], 16;" :: "r"(s), "l"(g));
}
#define CP_COMMIT() asm volatile("cp.async.commit_group;" ::: "memory")
#define CP_WAIT1()  asm volatile("cp.async.wait_group 1;" ::: "memory")
#define CP_WAIT0()  asm volatile("cp.async.wait_group 0;" ::: "memory")

// ---------------------------------------------------------------------------
// Kernel 1: fused weight-convert + GroupNorm (R12 winner, unchanged).
// ---------------------------------------------------------------------------
__global__ void gnsplit_kernel(const float* __restrict__ x,
                               const float* __restrict__ w,
                               const float* __restrict__ bias,
                               const float* __restrict__ qw,
                               const float* __restrict__ ow) {
    int tid = threadIdx.x;
    if (blockIdx.x < 768) {
        int i = blockIdx.x * 256 + tid;
        g_wqh[i] = __float2half(qw[i]);
        if (i < CC * CC) g_woh[i] = __float2half(ow[i]);
        return;
    }
    int bg = blockIdx.x - 768;
    int bb = bg >> 5, g = bg & 31;
    const float4* xp = (const float4*)(x + ((size_t)bb * CC + g * 8) * TT);

    float s = 0.f, s2 = 0.f;
    for (int i = tid; i < 4096; i += 256) {
        float4 v = xp[i];
        s  += v.x + v.y + v.z + v.w;
        s2 += v.x * v.x + v.y * v.y + v.z * v.z + v.w * v.w;
    }
    __shared__ float rs[256], rs2[256];
    rs[tid] = s; rs2[tid] = s2;
    __syncthreads();
    for (int off = 128; off > 0; off >>= 1) {
        if (tid < off) { rs[tid] += rs[tid + off]; rs2[tid] += rs2[tid + off]; }
        __syncthreads();
    }
    float mu   = rs[0] * (1.f / 16384.f);
    float var  = rs2[0] * (1.f / 16384.f) - mu * mu;
    float rstd = rsqrtf(var + 1e-5f);

    size_t ob = ((size_t)bb * CC + g * 8) * TT;
    for (int i = tid; i < 4096; i += 256) {
        int c = g * 8 + (i >> 9);
        float wc = w[c] * rstd;
        float bc = bias[c] - mu * wc;
        float4 v = xp[i];
        uint32_t h01 = pack2f(v.x * wc + bc, v.y * wc + bc);
        uint32_t h23 = pack2f(v.z * wc + bc, v.w * wc + bc);
        *(uint2*)(g_nh + ob + (size_t)i * 4) = make_uint2(h01, h23);
    }
}

// ---------------------------------------------------------------------------
// Kernel 2: QKV projection, fp16 mma GEMM (f32 accum), M-tile 128 (M=16/warp),
// 2-stage cp.async pipeline. Loader strides FIXED: 16B chunk = 8 halves.
//   A tile 128x32: 512 chunks -> 2/thread (r=f>>2, c=(f&3)*8)
//   B tile 32x64 : 256 chunks -> 1/thread (r=tid>>3, c=(tid&7)*8)
// ---------------------------------------------------------------------------
__global__ void __launch_bounds__(256) qkv_gemm_kernel() {
    int batch = blockIdx.z;
    int n0 = blockIdx.x * 64, mb = blockIdx.y * 128;
    const __half* Bh_g = g_nh + (size_t)batch * CC * TT;

    __shared__ __align__(16) __half As[2][128][40];
    __shared__ __align__(16) __half Bs[2][32][72];

    int tid  = threadIdx.x;
    int lane = tid & 31;
    int warp = tid >> 5;
    int m0   = warp * 16;

    int ar0 = tid >> 2,           ac0 = (tid & 3) * 8;
    int ar1 = (tid + 256) >> 2,   ac1 = ((tid + 256) & 3) * 8;
    int br  = tid >> 3,           bc  = (tid & 7) * 8;
    const __half* gA0 = g_wqh + (size_t)(mb + ar0) * CC + ac0;
    const __half* gA1 = g_wqh + (size_t)(mb + ar1) * CC + ac1;
    const __half* gB  = Bh_g + (size_t)br * TT + n0 + bc;
    uint32_t sA0[2], sA1[2], sB[2];
    #pragma unroll
    for (int s = 0; s < 2; s++) {
        sA0[s] = su(&As[s][ar0][ac0]);
        sA1[s] = su(&As[s][ar1][ac1]);
        sB[s]  = su(&Bs[s][br][bc]);
    }

    // prologue: stage 0 (k = 0)
    cpa16(sA0[0], gA0); cpa16(sA1[0], gA1); cpa16(sB[0], gB);
    CP_COMMIT();

    float Sf[8][4] = {};

    int a_r = lane & 15, a_h = (lane >> 4) * 8;
    int b_d = ((lane >> 3) & 1) * 8 + (lane & 7);
    int b_j = (lane >> 4);

    for (int ks = 0; ks < 8; ks++) {
        if (ks + 1 < 8) {
            int k1 = (ks + 1) * 32;
            int s = (ks + 1) & 1;
            cpa16(sA0[s], gA0 + k1);
            cpa16(sA1[s], gA1 + k1);
            cpa16(sB[s],  gB + (size_t)k1 * TT);
            CP_COMMIT();
            CP_WAIT1();
        } else {
            CP_WAIT0();
        }
        __syncthreads();
        int sb = ks & 1;

        #pragma unroll
        for (int kc = 0; kc < 2; kc++) {
            int kb = kc * 16;
            uint32_t a0, a1, a2, a3;
            ldsm4(a0, a1, a2, a3, su(&As[sb][m0 + a_r][kb + a_h]));
            #pragma unroll
            for (int jj = 0; jj < 8; jj += 2) {
                int cb = (jj + b_j) * 8;
                uint32_t k0r, k1r, k2r, k3r;
                ldsm4t(k0r, k1r, k2r, k3r, su(&Bs[sb][kb + b_d][cb]));
                mma16816(Sf[jj],     a0, a1, a2, a3, k0r, k1r);
                mma16816(Sf[jj + 1], a0, a1, a2, a3, k2r, k3r);
            }
        }
        __syncthreads();   // release buffer sb for prefetch at ks+2
    }

    int r0 = lane >> 2, tig = lane & 3;
    #pragma unroll
    for (int half = 0; half < 2; half++) {
        int o = mb + m0 + r0 + half * 8;
        int hd = o / 96, rr = o % 96;
        int role = rr >> 5, d = rr & 31;
        float sc = (role == 0) ? (LOG2E / 16.0f) : 1.0f;
        size_t base = ((((size_t)batch * HH + hd) * 3 + role) * DD + d) * TT + n0 + tig * 2;
        #pragma unroll
        for (int j = 0; j < 8; j++) {
            *(uint32_t*)(g_sph + base + j * 8) =
                pack2f(Sf[j][2 * half] * sc, Sf[j][2 * half + 1] * sc);
        }
    }
}

// ---------------------------------------------------------------------------
// Kernel 3: flash attention — f16-accumulator mma mainloop (R12 winner,
// unchanged).
// ---------------------------------------------------------------------------
struct KVStage {
    __half Kh[32][72], Vh[32][72];
};
#define ROWB 144   // bytes per smem row (72 halves)

__global__ void __launch_bounds__(256) attn_kernel() {
    int lt0 = blockIdx.x * 128, h = blockIdx.y, batch = blockIdx.z;
    size_t hb = ((size_t)batch * HH + h) * 3 * DD * TT;
    const __half* qhp = g_sph + hb;
    const __half* khp = qhp + DD * TT;
    const __half* vhp = qhp + 2 * DD * TT;

    __shared__ __align__(16) __half Qh[32][136];
    __shared__ __align__(16) KVStage st[2];

    int tid  = threadIdx.x;
    int lane = tid & 31;
    int warp = tid >> 5;      // 0..7
    int m0   = warp * 16;

    int row = tid >> 3;               // 0..31
    int cbl = (tid & 7) * 8;
    const __half* gK = khp + (size_t)row * TT + cbl;
    const __half* gV = vhp + (size_t)row * TT + cbl;
    uint32_t aK[2], aV[2];
    #pragma unroll
    for (int s = 0; s < 2; s++) {
        aK[s] = su(&st[s].Kh[row][cbl]);
        aV[s] = su(&st[s].Vh[row][cbl]);
    }

    cpa16(aK[0], gK); cpa16(aV[0], gV);
    CP_COMMIT();

    #pragma unroll
    for (int t2 = 0; t2 < 2; t2++) {
        int f = tid + t2 * 256;
        int d = f >> 4, c = (f & 15) * 8;
        *(uint4*)&Qh[d][c] = *(const uint4*)(qhp + (size_t)d * TT + lt0 + c);
    }
    __syncthreads();

    int a_d = ((lane >> 4) & 1) * 8 + (lane & 7);
    int a_c = m0 + ((lane >> 3) & 1) * 8;
    uint32_t qf[2][4];
    #pragma unroll
    for (int kc = 0; kc < 2; kc++) {
        ldsm4t(qf[kc][0], qf[kc][1], qf[kc][2], qf[kc][3], su(&Qh[kc * 16 + a_d][a_c]));
    }

    int b_d = ((lane >> 3) & 1) * 8 + (lane & 7);
    int b_j = (lane >> 4);
    int b4 = lane & 7;
    int bg = lane >> 3;
    uint32_t baseK[2], baseV[2];
    #pragma unroll
    for (int s = 0; s < 2; s++) {
        baseK[s] = su(&st[s].Kh[0][0]) + b_d * ROWB + b_j * 16;
        baseV[s] = su(&st[s].Vh[0][0]) + ((bg >> 1) * 8 + b4) * ROWB + (bg & 1) * 16;
    }

    float sum0 = 0.f, sum1 = 0.f;
    uint32_t Op[4][2] = {};

    for (int xt = 0; xt < 32; xt++) {
        if (xt + 1 < 32) {
            int xo = (xt + 1) * 64;
            int s = (xt + 1) & 1;
            cpa16(aK[s], gK + xo); cpa16(aV[s], gV + xo);
            CP_COMMIT();
            CP_WAIT1();
        } else {
            CP_WAIT0();
        }
        __syncthreads();
        int sb = xt & 1;

        uint32_t Sp[8][2] = {};
        #pragma unroll
        for (int kc = 0; kc < 2; kc++) {
            #pragma unroll
            for (int jj = 0; jj < 8; jj += 2) {
                uint32_t k0, k1, k2, k3;
                ldsm4t(k0, k1, k2, k3, baseK[sb] + kc * 16 * ROWB + jj * 16);
                mma16816h(Sp[jj][0],     Sp[jj][1],
                          qf[kc][0], qf[kc][1], qf[kc][2], qf[kc][3], k0, k1);
                mma16816h(Sp[jj + 1][0], Sp[jj + 1][1],
                          qf[kc][0], qf[kc][1], qf[kc][2], qf[kc][3], k2, k3);
            }
        }

        uint32_t acc0 = 0, acc1 = 0;
        #pragma unroll
        for (int kc = 0; kc < 4; kc++) {
            int j0 = 2 * kc, j1 = 2 * kc + 1;
            uint32_t p0 = ex2h2(Sp[j0][0]);
            uint32_t p1 = ex2h2(Sp[j0][1]);
            uint32_t p2 = ex2h2(Sp[j1][0]);
            uint32_t p3 = ex2h2(Sp[j1][1]);
            acc0 = hadd2(acc0, p0); acc0 = hadd2(acc0, p2);
            acc1 = hadd2(acc1, p1); acc1 = hadd2(acc1, p3);
            #pragma unroll
            for (int np = 0; np < 2; np++) {
                uint32_t h0, h1, h2, h3;
                ldsm4(h0, h1, h2, h3, baseV[sb] + np * 16 * ROWB + kc * 32);
                mma16816h(Op[np * 2][0],     Op[np * 2][1],     p0, p1, p2, p3, h0, h1);
                mma16816h(Op[np * 2 + 1][0], Op[np * 2 + 1][1], p0, p1, p2, p3, h2, h3);
            }
        }
        {
            __half2 v0 = *(__half2*)&acc0;
            __half2 v1 = *(__half2*)&acc1;
            sum0 += __low2float(v0) + __high2float(v0);
            sum1 += __low2float(v1) + __high2float(v1);
        }
        __syncthreads();
    }

    sum0 += __shfl_xor_sync(0xffffffffu, sum0, 1);
    sum0 += __shfl_xor_sync(0xffffffffu, sum0, 2);
    sum1 += __shfl_xor_sync(0xffffffffu, sum1, 1);
    sum1 += __shfl_xor_sync(0xffffffffu, sum1, 2);
    float inv0 = 1.f / sum0, inv1 = 1.f / sum1;

    float (*Os)[33] = (float(*)[33])&st[0];
    int r0w = lane >> 2, tig = lane & 3;
    #pragma unroll
    for (int nd = 0; nd < 4; nd++) {
        int col = nd * 8 + tig * 2;
        __half2 o0 = *(__half2*)&Op[nd][0];
        __half2 o1 = *(__half2*)&Op[nd][1];
        Os[m0 + r0w][col]         = __low2float(o0)  * inv0;
        Os[m0 + r0w][col + 1]     = __high2float(o0) * inv0;
        Os[m0 + r0w + 8][col]     = __low2float(o1)  * inv1;
        Os[m0 + r0w + 8][col + 1] = __high2float(o1) * inv1;
    }
    __syncthreads();
    size_t ob = ((size_t)batch * CC + h * DD) * TT;
    #pragma unroll
    for (int t4 = 0; t4 < 4; t4++) {
        int f = tid + t4 * 256;
        int d = f >> 5, lq = (f & 31) * 4;
        uint32_t u01 = pack2f(Os[lq][d],     Os[lq + 1][d]);
        uint32_t u23 = pack2f(Os[lq + 2][d], Os[lq + 3][d]);
        *(uint2*)(g_ath + ob + (size_t)d * TT + lt0 + lq) = make_uint2(u01, u23);
    }
}

// ---------------------------------------------------------------------------
// Kernel 4: out projection, fp16 mma GEMM (f32 accum) + bias + residual,
// 2-stage cp.async pipeline. Loader strides FIXED (8-half chunks).
// ---------------------------------------------------------------------------
__global__ void __launch_bounds__(256) out_gemm_kernel(const float* __restrict__ ob,
                                                       const float* __restrict__ xres,
                                                       float* __restrict__ out) {
    int batch = blockIdx.z;
    int n0 = blockIdx.x * 64, mb = blockIdx.y * 128;
    const __half* Bh_g = g_ath + (size_t)batch * CC * TT;

    __shared__ __align__(16) __half As[2][128][40];
    __shared__ __align__(16) __half Bs[2][32][72];

    int tid  = threadIdx.x;
    int lane = tid & 31;
    int warp = tid >> 5;
    int m0   = warp * 16;

    int ar0 = tid >> 2,           ac0 = (tid & 3) * 8;
    int ar1 = (tid + 256) >> 2,   ac1 = ((tid + 256) & 3) * 8;
    int br  = tid >> 3,           bc  = (tid & 7) * 8;
    const __half* gA0 = g_woh + (size_t)(mb + ar0) * CC + ac0;
    const __half* gA1 = g_woh + (size_t)(mb + ar1) * CC + ac1;
    const __half* gB  = Bh_g + (size_t)br * TT + n0 + bc;
    uint32_t sA0[2], sA1[2], sB[2];
    #pragma unroll
    for (int s = 0; s < 2; s++) {
        sA0[s] = su(&As[s][ar0][ac0]);
        sA1[s] = su(&As[s][ar1][ac1]);
        sB[s]  = su(&Bs[s][br][bc]);
    }

    cpa16(sA0[0], gA0); cpa16(sA1[0], gA1); cpa16(sB[0], gB);
    CP_COMMIT();

    float Sf[8][4] = {};

    int a_r = lane & 15, a_h = (lane >> 4) * 8;
    int b_d = ((lane >> 3) & 1) * 8 + (lane & 7);
    int b_j = (lane >> 4);

    for (int ks = 0; ks < 8; ks++) {
        if (ks + 1 < 8) {
            int k1 = (ks + 1) * 32;
            int s = (ks + 1) & 1;
            cpa16(sA0[s], gA0 + k1);
            cpa16(sA1[s], gA1 + k1);
            cpa16(sB[s],  gB + (size_t)k1 * TT);
            CP_COMMIT();
            CP_WAIT1();
        } else {
            CP_WAIT0();
        }
        __syncthreads();
        int sb = ks & 1;

        #pragma unroll
        for (int kc = 0; kc < 2; kc++) {
            int kb = kc * 16;
            uint32_t a0, a1, a2, a3;
            ldsm4(a0, a1, a2, a3, su(&As[sb][m0 + a_r][kb + a_h]));
            #pragma unroll
            for (int jj = 0; jj < 8; jj += 2) {
                int cb = (jj + b_j) * 8;
                uint32_t k0r, k1r, k2r, k3r;
                ldsm4t(k0r, k1r, k2r, k3r, su(&Bs[sb][kb + b_d][cb]));
                mma16816(Sf[jj],     a0, a1, a2, a3, k0r, k1r);
                mma16816(Sf[jj + 1], a0, a1, a2, a3, k2r, k3r);
            }
        }
        __syncthreads();   // release buffer sb for prefetch at ks+2
    }

    int r0 = lane >> 2, tig = lane & 3;
    #pragma unroll
    for (int half = 0; half < 2; half++) {
        int m = mb + m0 + r0 + half * 8;
        float bsv = ob[m];
        size_t rowoff = ((size_t)batch * CC + m) * TT + n0 + tig * 2;
        #pragma unroll
        for (int j = 0; j < 8; j++) {
            float2 r = *(const float2*)(xres + rowoff + j * 8);
            float2 o = make_float2(Sf[j][2 * half] + bsv + r.x,
                                   Sf[j][2 * half + 1] + bsv + r.y);
            *(float2*)(out + rowoff + j * 8) = o;
        }
    }
}

// ---------------------------------------------------------------------------
extern "C" void kernel_launch(void* const* d_in, const int* in_sizes, int n_in,
                              void* d_out, int out_size) {
    const float* x     = (const float*)d_in[0];
    const float* gn_w  = (const float*)d_in[1];
    const float* gn_b  = (const float*)d_in[2];
    const float* qkv_w = (const float*)d_in[3];
    const float* out_w = (const float*)d_in[4];
    const float* out_b = (const float*)d_in[5];
    float* out = (float*)d_out;

    gnsplit_kernel<<<896, 256>>>(x, gn_w, gn_b, qkv_w, out_w);
    qkv_gemm_kernel<<<dim3(TT / 64, M3 / 128, BB), 256>>>();
    attn_kernel<<<dim3(TT / 128, HH, BB), 256>>>();
    out_gemm_kernel<<<dim3(TT / 64, CC / 128, BB), 256>>>(out_b, x, out);
}